// round 15
// baseline (speedup 1.0000x reference)
#include <cuda_runtime.h>
#include <cuda_fp16.h>
#include <math.h>
#include <stdint.h>

#define DIM   512
#define HEADS 8
#define DQ    64
#define SEQ   4096
#define BATCH 2
#define NTOK  (BATCH * SEQ)   // 8192

// Scratch (allocation-free rule: __device__ globals)
__device__ __half g_q [NTOK * DIM];          // Q fp16, pre-scaled by 0.125*log2e
__device__ __half g_k [NTOK * DIM];          // K fp16
__device__ __half g_vt[NTOK * DIM];          // V transposed fp16: [b*512+m][4096]
__device__ __half g_ao[NTOK * DIM];          // attention output fp16
__device__ __half g_x16[NTOK * DIM];         // X pre-rounded to fp16
__device__ __half g_w16[4 * DIM * DIM];      // Wq,Wk,Wv,Wo pre-rounded fp16 (stacked)

// ---------------------------------------------------------------------------
// helpers
// ---------------------------------------------------------------------------
__device__ __forceinline__ float ex2f(float x) {
    float y; asm("ex2.approx.ftz.f32 %0, %1;" : "=f"(y) : "f"(x)); return y;
}

__device__ __forceinline__ uint32_t pack_f16(float lo, float hi) {
    __half2 h = __floats2half2_rn(lo, hi);
    return *(uint32_t*)&h;
}

__device__ __forceinline__ void ldsm_x4(uint32_t r[4], const void* p) {
    uint32_t a = (uint32_t)__cvta_generic_to_shared(p);
    asm volatile("ldmatrix.sync.aligned.m8n8.x4.shared.b16 {%0,%1,%2,%3}, [%4];"
                 : "=r"(r[0]), "=r"(r[1]), "=r"(r[2]), "=r"(r[3])
                 : "r"(a) : "memory");
}

__device__ __forceinline__ void mma_f16(float c[4], const uint32_t a[4],
                                        uint32_t b0, uint32_t b1) {
    asm volatile("mma.sync.aligned.m16n8k16.row.col.f32.f16.f16.f32 "
                 "{%0,%1,%2,%3}, {%4,%5,%6,%7}, {%8,%9}, {%0,%1,%2,%3};"
                 : "+f"(c[0]), "+f"(c[1]), "+f"(c[2]), "+f"(c[3])
                 : "r"(a[0]), "r"(a[1]), "r"(a[2]), "r"(a[3]), "r"(b0), "r"(b1));
}

__device__ __forceinline__ void cp16(void* smem_dst, const void* gsrc) {
    uint32_t a = (uint32_t)__cvta_generic_to_shared(smem_dst);
    asm volatile("cp.async.cg.shared.global [%0], [%1], 16;" :: "r"(a), "l"(gsrc));
}
#define CP_COMMIT() asm volatile("cp.async.commit_group;")
#define CP_WAIT1()  asm volatile("cp.async.wait_group 1;")
#define CP_WAIT0()  asm volatile("cp.async.wait_group 0;")

// ---------------------------------------------------------------------------
// Pre-round fp32 -> fp16 (8 elems/thread)
// ---------------------------------------------------------------------------
__global__ __launch_bounds__(256) void round_x16_kernel(
    const float* __restrict__ s, __half* __restrict__ d)
{
    int i = (blockIdx.x * 256 + threadIdx.x) * 8;
    float4 a = *(const float4*)&s[i];
    float4 b = *(const float4*)&s[i + 4];
    __half2 h0 = __floats2half2_rn(a.x, a.y);
    __half2 h1 = __floats2half2_rn(a.z, a.w);
    __half2 h2 = __floats2half2_rn(b.x, b.y);
    __half2 h3 = __floats2half2_rn(b.z, b.w);
    uint4 u = make_uint4(*(uint32_t*)&h0, *(uint32_t*)&h1,
                         *(uint32_t*)&h2, *(uint32_t*)&h3);
    *(uint4*)&d[i] = u;
}

__global__ __launch_bounds__(256) void round_w16_kernel(
    const float* __restrict__ Wq, const float* __restrict__ Wk,
    const float* __restrict__ Wv, const float* __restrict__ Wo,
    __half* __restrict__ d)
{
    const float* src = (blockIdx.y == 0) ? Wq :
                       (blockIdx.y == 1) ? Wk :
                       (blockIdx.y == 2) ? Wv : Wo;
    int i = (blockIdx.x * 256 + threadIdx.x) * 8;
    float4 a = *(const float4*)&src[i];
    float4 b = *(const float4*)&src[i + 4];
    __half2 h0 = __floats2half2_rn(a.x, a.y);
    __half2 h1 = __floats2half2_rn(a.z, a.w);
    __half2 h2 = __floats2half2_rn(b.x, b.y);
    __half2 h3 = __floats2half2_rn(b.z, b.w);
    uint4 u = make_uint4(*(uint32_t*)&h0, *(uint32_t*)&h1,
                         *(uint32_t*)&h2, *(uint32_t*)&h3);
    *(uint4*)&d[(size_t)blockIdx.y * (DIM * DIM) + i] = u;
}

// ---------------------------------------------------------------------------
// fp16 GEMM core: 128x64 tile, 8 warps, k-steps of 32, 3-deep ring,
// ONE barrier per k-step.  C[n,m] = sum_k X[n,k]*W[m,k]  (K = 512)
// ---------------------------------------------------------------------------
#define GHP 40   // fp16 shared pitch (halves)
#define GEMM_SMEM ((3*128 + 3*64) * GHP * sizeof(__half))   // 46080 B

__device__ __forceinline__ void gemm_mainloop16(
    const __half* __restrict__ X, const __half* __restrict__ W,
    int n0, int wrow0, __half* sm, float c[8][4])
{
    __half* Xs[3] = { sm, sm + 128 * GHP, sm + 256 * GHP };
    __half* Ws[3] = { sm + 384 * GHP, sm + 448 * GHP, sm + 512 * GHP };

    const int tid = threadIdx.x;
    const int L   = tid & 31;
    const int wid = tid >> 5;

    const int arow = wid * 16 + ((L >> 3) & 1) * 8 + (L & 7);
    const int aoff = ((L >> 4) & 1) * 8;
    const int brow = L & 7;
    const int bcol = ((L >> 3) & 1) * 8 + ((L >> 4) & 1) * 16;

    const int xr = tid >> 2, xch = (tid & 3) * 8;

    #pragma unroll
    for (int g = 0; g < 2; g++) {
        int k0 = g * 32;
        #pragma unroll
        for (int r = 0; r < 2; r++) {
            int e = tid + 256 * r;
            int row = e >> 2, ch = (e & 3) * 8;
            cp16(&Xs[g][row * GHP + ch],
                 &X[(size_t)(n0 + row) * DIM + k0 + ch]);
        }
        cp16(&Ws[g][xr * GHP + xch],
             &W[(size_t)(wrow0 + xr) * DIM + k0 + xch]);
        CP_COMMIT();
    }

    const int NK = DIM / 32;   // 16
    int cur = 0;
    for (int t = 0; t < NK; t++) {
        int nxt = cur + 1; if (nxt == 3) nxt = 0;
        if (t >= 1 && t + 1 < NK) {
            int k0 = (t + 1) * 32;
            #pragma unroll
            for (int r = 0; r < 2; r++) {
                int e = tid + 256 * r;
                int row = e >> 2, ch = (e & 3) * 8;
                cp16(&Xs[nxt][row * GHP + ch],
                     &X[(size_t)(n0 + row) * DIM + k0 + ch]);
            }
            cp16(&Ws[nxt][xr * GHP + xch],
                 &W[(size_t)(wrow0 + xr) * DIM + k0 + xch]);
        }
        CP_COMMIT();
        CP_WAIT1();
        __syncthreads();

        const __half* Xb = Xs[cur];
        const __half* Wb = Ws[cur];

        uint32_t a0[4], a1[4];
        ldsm_x4(a0, &Xb[arow * GHP + aoff]);
        ldsm_x4(a1, &Xb[arow * GHP + 16 + aoff]);
        #pragma unroll
        for (int jp = 0; jp < 8; jp++) {
            uint32_t bf[4];
            ldsm_x4(bf, &Wb[(jp * 8 + brow) * GHP + bcol]);
            mma_f16(c[jp], a0, bf[0], bf[1]);
            mma_f16(c[jp], a1, bf[2], bf[3]);
        }
        cur = nxt;
    }
}

// ---------------------------------------------------------------------------
// Merged QKV projection.  Q -> fp16 (pre-scaled by 0.125*log2e), K -> fp16,
// V -> transposed fp16.
// ---------------------------------------------------------------------------
__global__ __launch_bounds__(256) void gemm_qkv(
    const __half* __restrict__ X, const __half* __restrict__ Wqkv,
    const float* __restrict__ bq, const float* __restrict__ bk,
    const float* __restrict__ bv,
    __half* __restrict__ Cq, __half* __restrict__ Ck,
    __half* __restrict__ Cvt)
{
    extern __shared__ __half smh[];
    const int tid = threadIdx.x;
    const int L   = tid & 31;
    const int wid = tid >> 5;
    const int n0  = blockIdx.x * 128;
    const int m0g = blockIdx.y * 64;          // 0..1535
    const int which = m0g >> 9;               // 0=Q 1=K 2=V
    const int m0  = m0g & 511;

    float c[8][4] = {};
    gemm_mainloop16(X, Wqkv, n0, m0g, smh, c);

    const int rlo  = n0 + wid * 16 + (L >> 2);
    const int colb = 2 * (L & 3);
    if (which == 0) {
        const float QS = 0.125f * 1.44269504088896f;
        #pragma unroll
        for (int j = 0; j < 8; j++) {
            int col = m0 + j * 8 + colb;
            float b0 = bq[col], b1 = bq[col + 1];
            *(__half2*)&Cq[(size_t)rlo * DIM + col] =
                __floats2half2_rn((c[j][0] + b0) * QS, (c[j][1] + b1) * QS);
            *(__half2*)&Cq[(size_t)(rlo + 8) * DIM + col] =
                __floats2half2_rn((c[j][2] + b0) * QS, (c[j][3] + b1) * QS);
        }
    } else if (which == 1) {
        #pragma unroll
        for (int j = 0; j < 8; j++) {
            int col = m0 + j * 8 + colb;
            float b0 = bk[col], b1 = bk[col + 1];
            *(__half2*)&Ck[(size_t)rlo * DIM + col] =
                __floats2half2_rn(c[j][0] + b0, c[j][1] + b1);
            *(__half2*)&Ck[(size_t)(rlo + 8) * DIM + col] =
                __floats2half2_rn(c[j][2] + b0, c[j][3] + b1);
        }
    } else {
        int b_lo = rlo >> 12, t_lo = rlo & 4095;
        int rhi = rlo + 8;
        int b_hi = rhi >> 12, t_hi = rhi & 4095;
        #pragma unroll
        for (int j = 0; j < 8; j++) {
            int m = m0 + j * 8 + colb;
            float bb0 = bv[m], bb1 = bv[m + 1];
            Cvt[(size_t)(b_lo * DIM + m)     * SEQ + t_lo] = __float2half(c[j][0] + bb0);
            Cvt[(size_t)(b_lo * DIM + m + 1) * SEQ + t_lo] = __float2half(c[j][1] + bb1);
            Cvt[(size_t)(b_hi * DIM + m)     * SEQ + t_hi] = __float2half(c[j][2] + bb0);
            Cvt[(size_t)(b_hi * DIM + m + 1) * SEQ + t_hi] = __float2half(c[j][3] + bb1);
        }
    }
}

// ---------------------------------------------------------------------------
// Output projection GEMM (fp32 out)
// ---------------------------------------------------------------------------
__global__ __launch_bounds__(256) void gemm_out(
    const __half* __restrict__ X, const __half* __restrict__ W,
    const float* __restrict__ bias, float* __restrict__ C)
{
    extern __shared__ __half smh[];
    const int tid = threadIdx.x;
    const int L   = tid & 31;
    const int wid = tid >> 5;
    const int n0  = blockIdx.x * 128;
    const int m0  = blockIdx.y * 64;

    float c[8][4] = {};
    gemm_mainloop16(X, W, n0, m0, smh, c);

    const int rlo  = n0 + wid * 16 + (L >> 2);
    const int colb = 2 * (L & 3);
    #pragma unroll
    for (int j = 0; j < 8; j++) {
        int col = m0 + j * 8 + colb;
        float b0 = bias[col], b1 = bias[col + 1];
        *(float2*)&C[(size_t)rlo * DIM + col] =
            make_float2(c[j][0] + b0, c[j][1] + b1);
        *(float2*)&C[(size_t)(rlo + 8) * DIM + col] =
            make_float2(c[j][2] + b0, c[j][3] + b1);
    }
}

// ---------------------------------------------------------------------------
// Flash attention: QK fp16, PV fp16, static-max softmax, register P.
// 128-KEY tiles: 2-deep K/V ring, ONE wait+barrier per 128 keys; compute
// runs as two sequential 64-key halves (identical math order to R13).
// Loop order [prefetch(t+1); compute(t); wait; sync]: the end-of-iter sync
// fences compute(t)'s readers before iter t+1 overwrites buf[t&1].
// ---------------------------------------------------------------------------
#define KP 72     // K pitch (halves): 64 data + 8 pad
#define VP 136    // V pitch (halves): 128 data + 8 pad
// Q 128*72 + K 2*128*72 + V 2*64*136 = 9216+18432+17408 halves = 90112 B
#define ATTN_SMEM ((128 * KP + 2 * 128 * KP + 2 * 64 * VP) * sizeof(__half))

__global__ __launch_bounds__(256, 2) void attn_tc(
    const __half* __restrict__ Q, const __half* __restrict__ K,
    const __half* __restrict__ Vt, __half* __restrict__ O)
{
    extern __shared__ __half smh[];
    __half* Qsm = smh;                                        // 128 x KP
    __half* Ksm[2] = { smh + 128 * KP, smh + 256 * KP };      // 128 x KP each
    __half* Vsm[2] = { smh + 384 * KP, smh + 384 * KP + 64 * VP };  // 64 x VP

    const int tid = threadIdx.x;
    const int L   = tid & 31;
    const int wid = tid >> 5;
    const int q0  = blockIdx.x * 128;
    const int h   = blockIdx.y;
    const int b   = blockIdx.z;
    const size_t qk_base = (size_t)b * SEQ * DIM + (size_t)h * DQ;
    const size_t vt_base = (size_t)(b * DIM + h * DQ) * SEQ;

    // load mappings
    const int krow = tid >> 3, kch = (tid & 7) * 8;   // K: 128 rows x 8 chunks, via e
    const int vrow = tid >> 2, vch = (tid & 3) * 8;   // V: 64 rows x 16 chunks (4/thread)

    // ---- prologue: Q + tile 0 (one group) ----
    #pragma unroll
    for (int r = 0; r < 4; r++) {
        int e = tid + 256 * r;
        int row = e >> 3, ch = (e & 7) * 8;
        cp16(&Qsm[row * KP + ch], &Q[qk_base + (size_t)(q0 + row) * DIM + ch]);
    }
    #pragma unroll
    for (int r = 0; r < 4; r++) {
        int e = tid + 256 * r;
        int row = e >> 3, ch = (e & 7) * 8;
        cp16(&Ksm[0][row * KP + ch], &K[qk_base + (size_t)row * DIM + ch]);
    }
    #pragma unroll
    for (int cc = 0; cc < 4; cc++)
        cp16(&Vsm[0][vrow * VP + vch + cc * 32],
             &Vt[vt_base + (size_t)vrow * SEQ + vch + cc * 32]);
    CP_COMMIT();
    CP_WAIT0();
    __syncthreads();

    // fragment lane mappings
    const int arow = wid * 16 + ((L >> 3) & 1) * 8 + (L & 7);
    const int aoff = ((L >> 4) & 1) * 8;
    const int vlrow = L & 7;
    const int vlcol = ((L >> 3) & 1) * 8 + ((L >> 4) & 1) * 16;

    uint32_t qA[4][4];
    #pragma unroll
    for (int kb = 0; kb < 4; kb++)
        ldsm_x4(qA[kb], &Qsm[arow * KP + kb * 16 + aoff]);

    float l_lo = 0.f, l_hi = 0.f;
    float o[8][4] = {};

    const int NT = SEQ / 128;   // 32 tiles of 128 keys
    for (int t = 0; t < NT; t++) {
        // prefetch tile t+1 into buf[(t+1)&1] (readers of that buf fenced
        // by the sync at the end of iter t-1)
        if (t + 1 < NT) {
            int nb = (t + 1) & 1;
            int k0 = (t + 1) * 128;
            #pragma unroll
            for (int r = 0; r < 4; r++) {
                int e = tid + 256 * r;
                int row = e >> 3, ch = (e & 7) * 8;
                cp16(&Ksm[nb][row * KP + ch],
                     &K[qk_base + (size_t)(k0 + row) * DIM + ch]);
            }
            #pragma unroll
            for (int cc = 0; cc < 4; cc++)
                cp16(&Vsm[nb][vrow * VP + vch + cc * 32],
                     &Vt[vt_base + (size_t)vrow * SEQ + k0 + vch + cc * 32]);
        }
        CP_COMMIT();

        const __half* Vb = Vsm[t & 1];

        // ---- two 64-key halves, identical to the R13 tile body ----
        #pragma unroll
        for (int hh = 0; hh < 2; hh++) {
            const __half* Kb = Ksm[t & 1] + hh * 64 * KP;

            // S = Q @ K^T
            float s[8][4] = {};
            #pragma unroll
            for (int ks2 = 0; ks2 < 2; ks2++) {
                #pragma unroll
                for (int jp = 0; jp < 8; jp++) {
                    uint32_t bf[4];
                    ldsm_x4(bf, &Kb[(jp * 8 + vlrow) * KP + ks2 * 32 + vlcol]);
                    mma_f16(s[jp], qA[ks2 * 2 + 0], bf[0], bf[1]);
                    mma_f16(s[jp], qA[ks2 * 2 + 1], bf[2], bf[3]);
                }
            }

            // Static-max softmax: p = 2^s
            uint32_t p[16];
            float sum_lo = 0.f, sum_hi = 0.f;
            #pragma unroll
            for (int kb = 0; kb < 4; kb++) {
                float e00 = ex2f(s[2*kb][0]),   e01 = ex2f(s[2*kb][1]);
                float e02 = ex2f(s[2*kb][2]),   e03 = ex2f(s[2*kb][3]);
                float e10 = ex2f(s[2*kb+1][0]), e11 = ex2f(s[2*kb+1][1]);
                float e12 = ex2f(s[2*kb+1][2]), e13 = ex2f(s[2*kb+1][3]);
                sum_lo += e00 + e01 + e10 + e11;
                sum_hi += e02 + e03 + e12 + e13;
                p[kb * 4 + 0] = pack_f16(e00, e01);
                p[kb * 4 + 1] = pack_f16(e02, e03);
                p[kb * 4 + 2] = pack_f16(e10, e11);
                p[kb * 4 + 3] = pack_f16(e12, e13);
            }
            l_lo += sum_lo;
            l_hi += sum_hi;

            // O += P @ V  (V columns hh*64 .. hh*64+63)
            #pragma unroll
            for (int m2 = 0; m2 < 2; m2++) {
                #pragma unroll
                for (int jp = 0; jp < 8; jp++) {
                    uint32_t bf[4];
                    ldsm_x4(bf, &Vb[(jp * 8 + vlrow) * VP + hh * 64 + m2 * 32 + vlcol]);
                    mma_f16(o[jp], &p[(2 * m2) * 4],     bf[0], bf[1]);
                    mma_f16(o[jp], &p[(2 * m2 + 1) * 4], bf[2], bf[3]);
                }
            }
        }

        // tile t+1 resident; sync fences compute(t) before next overwrite
        if (t + 1 < NT) {
            CP_WAIT0();
            __syncthreads();
        }
    }

    // epilogue: reduce lane-partial l, normalize, write fp16
    l_lo += __shfl_xor_sync(0xffffffffu, l_lo, 1);
    l_lo += __shfl_xor_sync(0xffffffffu, l_lo, 2);
    l_hi += __shfl_xor_sync(0xffffffffu, l_hi, 1);
    l_hi += __shfl_xor_sync(0xffffffffu, l_hi, 2);
    float il = 1.f / l_lo, ih = 1.f / l_hi;
    const int row = q0 + wid * 16 + (L >> 2);
    #pragma unroll
    for (int j = 0; j < 8; j++) {
        int col = j * 8 + 2 * (L & 3);
        *(__half2*)&O[qk_base + (size_t)row * DIM + col] =
            __floats2half2_rn(o[j][0] * il, o[j][1] * il);
        *(__half2*)&O[qk_base + (size_t)(row + 8) * DIM + col] =
            __floats2half2_rn(o[j][2] * ih, o[j][3] * ih);
    }
}

// ---------------------------------------------------------------------------
extern "C" void kernel_launch(void* const* d_in, const int* in_sizes, int n_in,
                              void* d_out, int out_size)
{
    const float* x  = (const float*)d_in[0];
    const float* Wq = (const float*)d_in[1];
    const float* bq = (const float*)d_in[2];
    const float* Wk = (const float*)d_in[3];
    const float* bk = (const float*)d_in[4];
    const float* Wv = (const float*)d_in[5];
    const float* bv = (const float*)d_in[6];
    const float* Wo = (const float*)d_in[7];
    const float* bo = (const float*)d_in[8];
    float* out = (float*)d_out;

    __half *qp, *kp, *vtp, *aop, *x16p, *w16p;
    cudaGetSymbolAddress((void**)&qp,   g_q);
    cudaGetSymbolAddress((void**)&kp,   g_k);
    cudaGetSymbolAddress((void**)&vtp,  g_vt);
    cudaGetSymbolAddress((void**)&aop,  g_ao);
    cudaGetSymbolAddress((void**)&x16p, g_x16);
    cudaGetSymbolAddress((void**)&w16p, g_w16);

    cudaFuncSetAttribute(gemm_qkv,
                         cudaFuncAttributeMaxDynamicSharedMemorySize,
                         (int)GEMM_SMEM);
    cudaFuncSetAttribute(gemm_out,
                         cudaFuncAttributeMaxDynamicSharedMemorySize,
                         (int)GEMM_SMEM);
    cudaFuncSetAttribute(attn_tc,
                         cudaFuncAttributeMaxDynamicSharedMemorySize,
                         (int)ATTN_SMEM);

    const int WSZ = DIM * DIM;
    round_x16_kernel<<<NTOK * DIM / 2048, 256>>>(x, x16p);
    round_w16_kernel<<<dim3(WSZ / 2048, 4), 256>>>(Wq, Wk, Wv, Wo, w16p);

    dim3 gridQKV(NTOK / 128, 3 * DIM / 64);   // 64 x 24
    gemm_qkv<<<gridQKV, 256, GEMM_SMEM>>>(x16p, w16p, bq, bk, bv, qp, kp, vtp);

    dim3 gridA(SEQ / 128, HEADS, BATCH);      // 32 x 8 x 2
    attn_tc<<<gridA, 256, ATTN_SMEM>>>(qp, kp, vtp, aop);

    dim3 gridP(NTOK / 128, DIM / 64);         // 64 x 8
    gemm_out<<<gridP, 256, GEMM_SMEM>>>(aop, w16p + 3 * (size_t)WSZ, bo, out);
}

// round 17
// speedup vs baseline: 1.0143x; 1.0143x over previous
#include <cuda_runtime.h>
#include <cuda_fp16.h>
#include <math.h>
#include <stdint.h>

#define DIM   512
#define HEADS 8
#define DQ    64
#define SEQ   4096
#define BATCH 2
#define NTOK  (BATCH * SEQ)   // 8192

// Scratch (allocation-free rule: __device__ globals)
__device__ __half g_q [NTOK * DIM];          // Q fp16, pre-scaled by 0.125*log2e
__device__ __half g_k [NTOK * DIM];          // K fp16
__device__ __half g_vt[NTOK * DIM];          // V transposed fp16: [b*512+m][4096]
__device__ __half g_ao[NTOK * DIM];          // attention output fp16
__device__ __half g_x16[NTOK * DIM];         // X pre-rounded to fp16
__device__ __half g_w16[4 * DIM * DIM];      // Wq,Wk,Wv,Wo pre-rounded fp16 (stacked)

// ---------------------------------------------------------------------------
// helpers
// ---------------------------------------------------------------------------
__device__ __forceinline__ float ex2f(float x) {
    float y; asm("ex2.approx.ftz.f32 %0, %1;" : "=f"(y) : "f"(x)); return y;
}

__device__ __forceinline__ uint32_t pack_f16(float lo, float hi) {
    __half2 h = __floats2half2_rn(lo, hi);
    return *(uint32_t*)&h;
}

__device__ __forceinline__ void ldsm_x4(uint32_t r[4], const void* p) {
    uint32_t a = (uint32_t)__cvta_generic_to_shared(p);
    asm volatile("ldmatrix.sync.aligned.m8n8.x4.shared.b16 {%0,%1,%2,%3}, [%4];"
                 : "=r"(r[0]), "=r"(r[1]), "=r"(r[2]), "=r"(r[3])
                 : "r"(a) : "memory");
}

__device__ __forceinline__ void mma_f16(float c[4], const uint32_t a[4],
                                        uint32_t b0, uint32_t b1) {
    asm volatile("mma.sync.aligned.m16n8k16.row.col.f32.f16.f16.f32 "
                 "{%0,%1,%2,%3}, {%4,%5,%6,%7}, {%8,%9}, {%0,%1,%2,%3};"
                 : "+f"(c[0]), "+f"(c[1]), "+f"(c[2]), "+f"(c[3])
                 : "r"(a[0]), "r"(a[1]), "r"(a[2]), "r"(a[3]), "r"(b0), "r"(b1));
}

__device__ __forceinline__ void cp16(void* smem_dst, const void* gsrc) {
    uint32_t a = (uint32_t)__cvta_generic_to_shared(smem_dst);
    asm volatile("cp.async.cg.shared.global [%0], [%1], 16;" :: "r"(a), "l"(gsrc));
}
#define CP_COMMIT() asm volatile("cp.async.commit_group;")
#define CP_WAIT1()  asm volatile("cp.async.wait_group 1;")

// ---------------------------------------------------------------------------
// Merged pre-rounding: X (NTOK*DIM) and the 4 stacked W's (4*DIM*DIM) in one
// launch.  Flat index -> source select; W chunks are WSZ-aligned per block.
// ---------------------------------------------------------------------------
#define WSZ   (DIM * DIM)           // 262144
#define XELEM (NTOK * DIM)          // 4194304

__global__ __launch_bounds__(256) void round_all_kernel(
    const float* __restrict__ x,
    const float* __restrict__ Wq, const float* __restrict__ Wk,
    const float* __restrict__ Wv, const float* __restrict__ Wo,
    __half* __restrict__ dx, __half* __restrict__ dw)
{
    int i = (blockIdx.x * 256 + threadIdx.x) * 8;
    const float* s;
    __half* d;
    int off;
    if (i < XELEM) {
        s = x; d = dx; off = i;
    } else {
        int wi = i - XELEM;
        int wsel = wi / WSZ;
        s = (wsel == 0) ? Wq : (wsel == 1) ? Wk : (wsel == 2) ? Wv : Wo;
        d = dw + (size_t)wsel * WSZ;
        off = wi - wsel * WSZ;
    }
    float4 a = *(const float4*)&s[off];
    float4 b = *(const float4*)&s[off + 4];
    __half2 h0 = __floats2half2_rn(a.x, a.y);
    __half2 h1 = __floats2half2_rn(a.z, a.w);
    __half2 h2 = __floats2half2_rn(b.x, b.y);
    __half2 h3 = __floats2half2_rn(b.z, b.w);
    uint4 u = make_uint4(*(uint32_t*)&h0, *(uint32_t*)&h1,
                         *(uint32_t*)&h2, *(uint32_t*)&h3);
    *(uint4*)&d[off] = u;
}

// ---------------------------------------------------------------------------
// fp16 GEMM core: 128x64 tile, 8 warps, k-steps of 32, 3-deep ring,
// ONE barrier per k-step.  C[n,m] = sum_k X[n,k]*W[m,k]  (K = 512)
// ---------------------------------------------------------------------------
#define GHP 40   // fp16 shared pitch (halves)
#define GEMM_SMEM ((3*128 + 3*64) * GHP * sizeof(__half))   // 46080 B

__device__ __forceinline__ void gemm_mainloop16(
    const __half* __restrict__ X, const __half* __restrict__ W,
    int n0, int wrow0, __half* sm, float c[8][4])
{
    __half* Xs[3] = { sm, sm + 128 * GHP, sm + 256 * GHP };
    __half* Ws[3] = { sm + 384 * GHP, sm + 448 * GHP, sm + 512 * GHP };

    const int tid = threadIdx.x;
    const int L   = tid & 31;
    const int wid = tid >> 5;

    const int arow = wid * 16 + ((L >> 3) & 1) * 8 + (L & 7);
    const int aoff = ((L >> 4) & 1) * 8;
    const int brow = L & 7;
    const int bcol = ((L >> 3) & 1) * 8 + ((L >> 4) & 1) * 16;

    const int xr = tid >> 2, xch = (tid & 3) * 8;

    #pragma unroll
    for (int g = 0; g < 2; g++) {
        int k0 = g * 32;
        #pragma unroll
        for (int r = 0; r < 2; r++) {
            int e = tid + 256 * r;
            int row = e >> 2, ch = (e & 3) * 8;
            cp16(&Xs[g][row * GHP + ch],
                 &X[(size_t)(n0 + row) * DIM + k0 + ch]);
        }
        cp16(&Ws[g][xr * GHP + xch],
             &W[(size_t)(wrow0 + xr) * DIM + k0 + xch]);
        CP_COMMIT();
    }

    const int NK = DIM / 32;   // 16
    int cur = 0;
    for (int t = 0; t < NK; t++) {
        int nxt = cur + 1; if (nxt == 3) nxt = 0;
        if (t >= 1 && t + 1 < NK) {
            int k0 = (t + 1) * 32;
            #pragma unroll
            for (int r = 0; r < 2; r++) {
                int e = tid + 256 * r;
                int row = e >> 2, ch = (e & 3) * 8;
                cp16(&Xs[nxt][row * GHP + ch],
                     &X[(size_t)(n0 + row) * DIM + k0 + ch]);
            }
            cp16(&Ws[nxt][xr * GHP + xch],
                 &W[(size_t)(wrow0 + xr) * DIM + k0 + xch]);
        }
        CP_COMMIT();
        CP_WAIT1();
        __syncthreads();

        const __half* Xb = Xs[cur];
        const __half* Wb = Ws[cur];

        uint32_t a0[4], a1[4];
        ldsm_x4(a0, &Xb[arow * GHP + aoff]);
        ldsm_x4(a1, &Xb[arow * GHP + 16 + aoff]);
        #pragma unroll
        for (int jp = 0; jp < 8; jp++) {
            uint32_t bf[4];
            ldsm_x4(bf, &Wb[(jp * 8 + brow) * GHP + bcol]);
            mma_f16(c[jp], a0, bf[0], bf[1]);
            mma_f16(c[jp], a1, bf[2], bf[3]);
        }
        cur = nxt;
    }
}

// ---------------------------------------------------------------------------
// Merged QKV projection.  Q -> fp16 (pre-scaled by 0.125*log2e), K -> fp16,
// V -> transposed fp16.
// ---------------------------------------------------------------------------
__global__ __launch_bounds__(256) void gemm_qkv(
    const __half* __restrict__ X, const __half* __restrict__ Wqkv,
    const float* __restrict__ bq, const float* __restrict__ bk,
    const float* __restrict__ bv,
    __half* __restrict__ Cq, __half* __restrict__ Ck,
    __half* __restrict__ Cvt)
{
    extern __shared__ __half smh[];
    const int tid = threadIdx.x;
    const int L   = tid & 31;
    const int wid = tid >> 5;
    const int n0  = blockIdx.x * 128;
    const int m0g = blockIdx.y * 64;          // 0..1535
    const int which = m0g >> 9;               // 0=Q 1=K 2=V
    const int m0  = m0g & 511;

    float c[8][4] = {};
    gemm_mainloop16(X, Wqkv, n0, m0g, smh, c);

    const int rlo  = n0 + wid * 16 + (L >> 2);
    const int colb = 2 * (L & 3);
    if (which == 0) {
        const float QS = 0.125f * 1.44269504088896f;
        #pragma unroll
        for (int j = 0; j < 8; j++) {
            int col = m0 + j * 8 + colb;
            float b0 = bq[col], b1 = bq[col + 1];
            *(__half2*)&Cq[(size_t)rlo * DIM + col] =
                __floats2half2_rn((c[j][0] + b0) * QS, (c[j][1] + b1) * QS);
            *(__half2*)&Cq[(size_t)(rlo + 8) * DIM + col] =
                __floats2half2_rn((c[j][2] + b0) * QS, (c[j][3] + b1) * QS);
        }
    } else if (which == 1) {
        #pragma unroll
        for (int j = 0; j < 8; j++) {
            int col = m0 + j * 8 + colb;
            float b0 = bk[col], b1 = bk[col + 1];
            *(__half2*)&Ck[(size_t)rlo * DIM + col] =
                __floats2half2_rn(c[j][0] + b0, c[j][1] + b1);
            *(__half2*)&Ck[(size_t)(rlo + 8) * DIM + col] =
                __floats2half2_rn(c[j][2] + b0, c[j][3] + b1);
        }
    } else {
        int b_lo = rlo >> 12, t_lo = rlo & 4095;
        int rhi = rlo + 8;
        int b_hi = rhi >> 12, t_hi = rhi & 4095;
        #pragma unroll
        for (int j = 0; j < 8; j++) {
            int m = m0 + j * 8 + colb;
            float bb0 = bv[m], bb1 = bv[m + 1];
            Cvt[(size_t)(b_lo * DIM + m)     * SEQ + t_lo] = __float2half(c[j][0] + bb0);
            Cvt[(size_t)(b_lo * DIM + m + 1) * SEQ + t_lo] = __float2half(c[j][1] + bb1);
            Cvt[(size_t)(b_hi * DIM + m)     * SEQ + t_hi] = __float2half(c[j][2] + bb0);
            Cvt[(size_t)(b_hi * DIM + m + 1) * SEQ + t_hi] = __float2half(c[j][3] + bb1);
        }
    }
}

// ---------------------------------------------------------------------------
// Output projection GEMM (fp32 out)
// ---------------------------------------------------------------------------
__global__ __launch_bounds__(256) void gemm_out(
    const __half* __restrict__ X, const __half* __restrict__ W,
    const float* __restrict__ bias, float* __restrict__ C)
{
    extern __shared__ __half smh[];
    const int tid = threadIdx.x;
    const int L   = tid & 31;
    const int wid = tid >> 5;
    const int n0  = blockIdx.x * 128;
    const int m0  = blockIdx.y * 64;

    float c[8][4] = {};
    gemm_mainloop16(X, W, n0, m0, smh, c);

    const int rlo  = n0 + wid * 16 + (L >> 2);
    const int colb = 2 * (L & 3);
    #pragma unroll
    for (int j = 0; j < 8; j++) {
        int col = m0 + j * 8 + colb;
        float b0 = bias[col], b1 = bias[col + 1];
        *(float2*)&C[(size_t)rlo * DIM + col] =
            make_float2(c[j][0] + b0, c[j][1] + b1);
        *(float2*)&C[(size_t)(rlo + 8) * DIM + col] =
            make_float2(c[j][2] + b0, c[j][3] + b1);
    }
}

// ---------------------------------------------------------------------------
// Flash attention (exact R13 best config): QK fp16, PV fp16, static-max
// softmax, register P, reg-resident Q frags, 3-deep 64-key K/V rings,
// ONE barrier per tile.
// ---------------------------------------------------------------------------
#define HP 72    // fp16 shared pitch (halves)
#define ATTN_SMEM (512 * HP * 2)   // Q 128 + K 3x64 + V 3x64 rows  = 73728 B

__global__ __launch_bounds__(256, 2) void attn_tc(
    const __half* __restrict__ Q, const __half* __restrict__ K,
    const __half* __restrict__ Vt, __half* __restrict__ O)
{
    extern __shared__ __half smh[];
    __half* Qsm = smh;                                   // 128 x HP
    __half* Ksm[3] = { smh + 128 * HP, smh + 192 * HP, smh + 256 * HP };
    __half* Vsm[3] = { smh + 320 * HP, smh + 384 * HP, smh + 448 * HP };

    const int tid = threadIdx.x;
    const int L   = tid & 31;
    const int wid = tid >> 5;
    const int q0  = blockIdx.x * 128;
    const int h   = blockIdx.y;
    const int b   = blockIdx.z;
    const size_t qk_base = (size_t)b * SEQ * DIM + (size_t)h * DQ;
    const size_t vt_base = (size_t)(b * DIM + h * DQ) * SEQ;

    const int vrow = tid >> 2, vc8 = (tid & 3) * 8;

    // ---- prologue group 0: Q tile + K0 + V0 ----
    #pragma unroll
    for (int r = 0; r < 4; r++) {
        int e = tid + 256 * r;
        int row = e >> 3, ch = (e & 7) * 8;
        cp16(&Qsm[row * HP + ch], &Q[qk_base + (size_t)(q0 + row) * DIM + ch]);
    }
    cp16(&Ksm[0][vrow * HP + vc8],      &K[qk_base + (size_t)vrow * DIM + vc8]);
    cp16(&Ksm[0][vrow * HP + vc8 + 32], &K[qk_base + (size_t)vrow * DIM + vc8 + 32]);
    cp16(&Vsm[0][vrow * HP + vc8],      &Vt[vt_base + (size_t)vrow * SEQ + vc8]);
    cp16(&Vsm[0][vrow * HP + vc8 + 32], &Vt[vt_base + (size_t)vrow * SEQ + vc8 + 32]);
    CP_COMMIT();
    // ---- prologue group 1: K1 + V1 ----
    cp16(&Ksm[1][vrow * HP + vc8],      &K[qk_base + (size_t)(64 + vrow) * DIM + vc8]);
    cp16(&Ksm[1][vrow * HP + vc8 + 32], &K[qk_base + (size_t)(64 + vrow) * DIM + vc8 + 32]);
    cp16(&Vsm[1][vrow * HP + vc8],      &Vt[vt_base + (size_t)vrow * SEQ + 64 + vc8]);
    cp16(&Vsm[1][vrow * HP + vc8 + 32], &Vt[vt_base + (size_t)vrow * SEQ + 64 + vc8 + 32]);
    CP_COMMIT();

    const int arow = wid * 16 + ((L >> 3) & 1) * 8 + (L & 7);
    const int aoff = ((L >> 4) & 1) * 8;
    const int vlrow = L & 7;
    const int vlcol = ((L >> 3) & 1) * 8 + ((L >> 4) & 1) * 16;

    float l_lo = 0.f, l_hi = 0.f;          // lane-partial row sums
    float o[8][4] = {};

    const int NT = SEQ / 64;   // 64
    int cur = 0;
    uint32_t qA[4][4];
    bool qloaded = false;

    for (int t = 0; t < NT; t++) {
        int nxt = cur + 1; if (nxt == 3) nxt = 0;
        if (t >= 1 && t + 1 < NT) {
            int k0 = (t + 1) * 64;
            cp16(&Ksm[nxt][vrow * HP + vc8],
                 &K[qk_base + (size_t)(k0 + vrow) * DIM + vc8]);
            cp16(&Ksm[nxt][vrow * HP + vc8 + 32],
                 &K[qk_base + (size_t)(k0 + vrow) * DIM + vc8 + 32]);
            cp16(&Vsm[nxt][vrow * HP + vc8],
                 &Vt[vt_base + (size_t)vrow * SEQ + k0 + vc8]);
            cp16(&Vsm[nxt][vrow * HP + vc8 + 32],
                 &Vt[vt_base + (size_t)vrow * SEQ + k0 + vc8 + 32]);
        }
        CP_COMMIT();
        CP_WAIT1();
        __syncthreads();

        if (!qloaded) {
            #pragma unroll
            for (int kb = 0; kb < 4; kb++)
                ldsm_x4(qA[kb], &Qsm[arow * HP + kb * 16 + aoff]);
            qloaded = true;
        }

        const __half* Kb = Ksm[cur];
        const __half* Vb = Vsm[cur];

        // S = Q @ K^T  (fp16; logits in log2 domain via Q pre-scale)
        float s[8][4] = {};
        #pragma unroll
        for (int ks2 = 0; ks2 < 2; ks2++) {
            #pragma unroll
            for (int jp = 0; jp < 8; jp++) {
                uint32_t bf[4];
                ldsm_x4(bf, &Kb[(jp * 8 + vlrow) * HP + ks2 * 32 + vlcol]);
                mma_f16(s[jp], qA[ks2 * 2 + 0], bf[0], bf[1]);
                mma_f16(s[jp], qA[ks2 * 2 + 1], bf[2], bf[3]);
            }
        }

        // Static-max softmax: p = 2^s directly
        uint32_t p[16];
        float sum_lo = 0.f, sum_hi = 0.f;
        #pragma unroll
        for (int kb = 0; kb < 4; kb++) {
            float e00 = ex2f(s[2*kb][0]),   e01 = ex2f(s[2*kb][1]);
            float e02 = ex2f(s[2*kb][2]),   e03 = ex2f(s[2*kb][3]);
            float e10 = ex2f(s[2*kb+1][0]), e11 = ex2f(s[2*kb+1][1]);
            float e12 = ex2f(s[2*kb+1][2]), e13 = ex2f(s[2*kb+1][3]);
            sum_lo += e00 + e01 + e10 + e11;
            sum_hi += e02 + e03 + e12 + e13;
            p[kb * 4 + 0] = pack_f16(e00, e01);
            p[kb * 4 + 1] = pack_f16(e02, e03);
            p[kb * 4 + 2] = pack_f16(e10, e11);
            p[kb * 4 + 3] = pack_f16(e12, e13);
        }
        l_lo += sum_lo;
        l_hi += sum_hi;

        // O += P @ V  (fp16)
        #pragma unroll
        for (int m2 = 0; m2 < 2; m2++) {
            #pragma unroll
            for (int jp = 0; jp < 8; jp++) {
                uint32_t bf[4];
                ldsm_x4(bf, &Vb[(jp * 8 + vlrow) * HP + m2 * 32 + vlcol]);
                mma_f16(o[jp], &p[(2 * m2) * 4],     bf[0], bf[1]);
                mma_f16(o[jp], &p[(2 * m2 + 1) * 4], bf[2], bf[3]);
            }
        }
        cur = nxt;
    }

    // epilogue: reduce lane-partial l, normalize, write fp16
    l_lo += __shfl_xor_sync(0xffffffffu, l_lo, 1);
    l_lo += __shfl_xor_sync(0xffffffffu, l_lo, 2);
    l_hi += __shfl_xor_sync(0xffffffffu, l_hi, 1);
    l_hi += __shfl_xor_sync(0xffffffffu, l_hi, 2);
    float il = 1.f / l_lo, ih = 1.f / l_hi;
    const int row = q0 + wid * 16 + (L >> 2);
    #pragma unroll
    for (int j = 0; j < 8; j++) {
        int col = j * 8 + 2 * (L & 3);
        *(__half2*)&O[qk_base + (size_t)row * DIM + col] =
            __floats2half2_rn(o[j][0] * il, o[j][1] * il);
        *(__half2*)&O[qk_base + (size_t)(row + 8) * DIM + col] =
            __floats2half2_rn(o[j][2] * ih, o[j][3] * ih);
    }
}

// ---------------------------------------------------------------------------
extern "C" void kernel_launch(void* const* d_in, const int* in_sizes, int n_in,
                              void* d_out, int out_size)
{
    const float* x  = (const float*)d_in[0];
    const float* Wq = (const float*)d_in[1];
    const float* bq = (const float*)d_in[2];
    const float* Wk = (const float*)d_in[3];
    const float* bk = (const float*)d_in[4];
    const float* Wv = (const float*)d_in[5];
    const float* bv = (const float*)d_in[6];
    const float* Wo = (const float*)d_in[7];
    const float* bo = (const float*)d_in[8];
    float* out = (float*)d_out;

    __half *qp, *kp, *vtp, *aop, *x16p, *w16p;
    cudaGetSymbolAddress((void**)&qp,   g_q);
    cudaGetSymbolAddress((void**)&kp,   g_k);
    cudaGetSymbolAddress((void**)&vtp,  g_vt);
    cudaGetSymbolAddress((void**)&aop,  g_ao);
    cudaGetSymbolAddress((void**)&x16p, g_x16);
    cudaGetSymbolAddress((void**)&w16p, g_w16);

    cudaFuncSetAttribute(gemm_qkv,
                         cudaFuncAttributeMaxDynamicSharedMemorySize,
                         (int)GEMM_SMEM);
    cudaFuncSetAttribute(gemm_out,
                         cudaFuncAttributeMaxDynamicSharedMemorySize,
                         (int)GEMM_SMEM);
    cudaFuncSetAttribute(attn_tc,
                         cudaFuncAttributeMaxDynamicSharedMemorySize,
                         (int)ATTN_SMEM);

    // One merged rounding launch: X + all four W's
    const int total8 = (XELEM + 4 * WSZ) / 8;     // 655360 threads
    round_all_kernel<<<total8 / 256, 256>>>(x, Wq, Wk, Wv, Wo, x16p, w16p);

    dim3 gridQKV(NTOK / 128, 3 * DIM / 64);   // 64 x 24
    gemm_qkv<<<gridQKV, 256, GEMM_SMEM>>>(x16p, w16p, bq, bk, bv, qp, kp, vtp);

    dim3 gridA(SEQ / 128, HEADS, BATCH);      // 32 x 8 x 2
    attn_tc<<<gridA, 256, ATTN_SMEM>>>(qp, kp, vtp, aop);

    dim3 gridP(NTOK / 128, DIM / 64);         // 64 x 8
    gemm_out<<<gridP, 256, GEMM_SMEM>>>(aop, w16p + 3 * (size_t)WSZ, bo, out);
}